// round 5
// baseline (speedup 1.0000x reference)
#include <cuda_runtime.h>

#define SEQ 4096
#define EMB 1024
#define NH  8
#define HD  128
#define NEGV -1e10f

// ---------------- scratch (no allocations allowed) ----------------
__device__ float g_q[SEQ * EMB];
__device__ float g_k[SEQ * EMB];
__device__ float g_v[SEQ * EMB];
__device__ float g_attn[SEQ * EMB];

// ---------------- GEMM: C[4096,1024] = A[4096,1024] @ W[1024,1024] ----------------
// BM=BN=128, BK=8, 256 threads, 8x8 microtile.
__global__ __launch_bounds__(256, 2) void gemm_kernel(const float* __restrict__ A,
                                                      const float* __restrict__ W,
                                                      float* __restrict__ C) {
    __shared__ __align__(16) float As[8][128];
    __shared__ __align__(16) float Bs[8][128];
    const int tid = threadIdx.x;
    const int bm = blockIdx.x * 128;
    const int bn = blockIdx.y * 128;
    const int ty = tid >> 4, tx = tid & 15;

    const int arow = tid >> 1;
    const int aseg = (tid & 1) << 2;
    const int brow = tid >> 5;
    const int bcol = (tid & 31) << 2;

    float acc[8][8];
#pragma unroll
    for (int i = 0; i < 8; i++)
#pragma unroll
        for (int j = 0; j < 8; j++) acc[i][j] = 0.f;

    const float* aptr = A + (size_t)(bm + arow) * EMB + aseg;
    const float* bptr = W + (size_t)brow * EMB + bn + bcol;

    for (int k0 = 0; k0 < EMB; k0 += 8) {
        float4 av = *(const float4*)(aptr + k0);
        float4 bv = *(const float4*)(bptr + (size_t)k0 * EMB);
        __syncthreads();
        As[aseg + 0][arow] = av.x;
        As[aseg + 1][arow] = av.y;
        As[aseg + 2][arow] = av.z;
        As[aseg + 3][arow] = av.w;
        *(float4*)(&Bs[brow][bcol]) = bv;
        __syncthreads();
#pragma unroll
        for (int kk = 0; kk < 8; kk++) {
            float4 a0 = *(const float4*)(&As[kk][ty * 8]);
            float4 a1 = *(const float4*)(&As[kk][ty * 8 + 4]);
            float4 b0 = *(const float4*)(&Bs[kk][tx * 8]);
            float4 b1 = *(const float4*)(&Bs[kk][tx * 8 + 4]);
            float aa[8] = {a0.x, a0.y, a0.z, a0.w, a1.x, a1.y, a1.z, a1.w};
            float bb[8] = {b0.x, b0.y, b0.z, b0.w, b1.x, b1.y, b1.z, b1.w};
#pragma unroll
            for (int i = 0; i < 8; i++)
#pragma unroll
                for (int j = 0; j < 8; j++) acc[i][j] += aa[i] * bb[j];
        }
    }
#pragma unroll
    for (int i = 0; i < 8; i++) {
        float* crow = C + (size_t)(bm + ty * 8 + i) * EMB + bn + tx * 8;
        float4 c0 = {acc[i][0], acc[i][1], acc[i][2], acc[i][3]};
        float4 c1 = {acc[i][4], acc[i][5], acc[i][6], acc[i][7]};
        *(float4*)(crow) = c0;
        *(float4*)(crow + 4) = c1;
    }
}

// ---------------- RoPE in-place on g_q, g_k ----------------
__global__ void rope_kernel(const float* __restrict__ cosb, const float* __restrict__ sinb) {
    int idx = blockIdx.x * blockDim.x + threadIdx.x;  // 2 * 4096 * 8 * 64
    if (idx >= 2 * SEQ * NH * 64) return;
    int t = idx >> 21;          // tensor: 0=q, 1=k  (2^21 pairs each)
    int rem = idx & 2097151;
    int s = rem >> 9;           // 512 pairs per position
    int r2 = rem & 511;
    int h = r2 >> 6;
    int d = r2 & 63;
    float* p = t ? g_k : g_q;
    int base = s * EMB + h * HD + d;
    float a = p[base];
    float b = p[base + 64];
    float c = cosb[s * 64 + d];
    float sn = sinb[s * 64 + d];
    p[base] = a * c - b * sn;          // d < 64: q*cos - q[d+64]*sin
    p[base + 64] = b * c + a * sn;     // d >= 64: q*cos + q[d-64]*sin
}

// ---------------- causal flash attention, fp32, BM=BN=64 ----------------
__global__ __launch_bounds__(256, 2) void flash_kernel(const float* __restrict__ qb,
                                                       const float* __restrict__ kb,
                                                       const float* __restrict__ vb,
                                                       float* __restrict__ ob) {
    extern __shared__ __align__(16) float fsm[];
    float* Qs  = fsm;            // [kk][m] 128x64 (pre-scaled)
    float* KVs = fsm + 8192;     // K phase: [kk][n] 128x64 ; V phase: [key][c] 64x128
    float* Ps  = fsm + 16384;    // [key][m] 64x64
    float* red = fsm + 20480;    // [m][16]
    float* mprev = fsm + 21504;  // [64]
    float* lsum  = fsm + 21568;  // [64]
    float* alph  = fsm + 21632;  // [64]   (total 21696 floats = 86784 B)

    const int tid = threadIdx.x;
    const int qbk = (int)gridDim.x - 1 - (int)blockIdx.x;  // longest blocks first
    const int h = blockIdx.y;
    const int qr0 = qbk * 64;
    const int ty = tid >> 4, tx = tid & 15;
    const int ty4 = ty * 4, tx4 = tx * 4, tx8 = tx * 8;
    const float scale = 0.08838834764831845f;  // 1/sqrt(128)

    // load + scale Q tile, transposed [kk][m]
#pragma unroll
    for (int rep = 0; rep < 8; rep++) {
        int p = rep * 256 + tid;
        int r = p >> 5;
        int kk4 = (p & 31) << 2;
        float4 v = *(const float4*)(qb + (size_t)(qr0 + r) * EMB + h * HD + kk4);
        Qs[(kk4 + 0) * 64 + r] = v.x * scale;
        Qs[(kk4 + 1) * 64 + r] = v.y * scale;
        Qs[(kk4 + 2) * 64 + r] = v.z * scale;
        Qs[(kk4 + 3) * 64 + r] = v.w * scale;
    }
    if (tid < 64) { mprev[tid] = -1e30f; lsum[tid] = 0.f; }

    float o[4][8];
#pragma unroll
    for (int i = 0; i < 4; i++)
#pragma unroll
        for (int j = 0; j < 8; j++) o[i][j] = 0.f;

    for (int kt = 0; kt <= qbk; kt++) {
        const int kn0 = kt * 64;
        __syncthreads();  // KVs/Ps free (prev PV done), Qs ready (iter 0)
        // load K tile transposed [kk][n]
#pragma unroll
        for (int rep = 0; rep < 8; rep++) {
            int p = rep * 256 + tid;
            int n = p >> 5;
            int kk4 = (p & 31) << 2;
            float4 v = *(const float4*)(kb + (size_t)(kn0 + n) * EMB + h * HD + kk4);
            KVs[(kk4 + 0) * 64 + n] = v.x;
            KVs[(kk4 + 1) * 64 + n] = v.y;
            KVs[(kk4 + 2) * 64 + n] = v.z;
            KVs[(kk4 + 3) * 64 + n] = v.w;
        }
        __syncthreads();

        // S = Q K^T (already scaled via Q)
        float s[4][4];
#pragma unroll
        for (int i = 0; i < 4; i++)
#pragma unroll
            for (int j = 0; j < 4; j++) s[i][j] = 0.f;
#pragma unroll 4
        for (int kk = 0; kk < 128; kk++) {
            float4 a = *(const float4*)(Qs + kk * 64 + ty4);
            float4 b = *(const float4*)(KVs + kk * 64 + tx4);
            float aa[4] = {a.x, a.y, a.z, a.w};
            float bb[4] = {b.x, b.y, b.z, b.w};
#pragma unroll
            for (int i = 0; i < 4; i++)
#pragma unroll
                for (int j = 0; j < 4; j++) s[i][j] += aa[i] * bb[j];
        }

        if (kt == qbk) {  // diagonal tile: mask key > query
#pragma unroll
            for (int i = 0; i < 4; i++)
#pragma unroll
                for (int j = 0; j < 4; j++)
                    if (tx4 + j > ty4 + i) s[i][j] = -1e30f;
        }

        // row-max partials
#pragma unroll
        for (int i = 0; i < 4; i++) {
            float pm = fmaxf(fmaxf(s[i][0], s[i][1]), fmaxf(s[i][2], s[i][3]));
            red[(ty4 + i) * 16 + tx] = pm;
        }
        __syncthreads();
        if (tid < 64) {
            float mrow = red[tid * 16];
#pragma unroll
            for (int t = 1; t < 16; t++) mrow = fmaxf(mrow, red[tid * 16 + t]);
            float mold = mprev[tid];
            float mnew = fmaxf(mold, mrow);
            mprev[tid] = mnew;
            alph[tid] = __expf(mold - mnew);
        }
        __syncthreads();

        // V tile load (reuse KVs; all K reads completed before red-sync)
#pragma unroll
        for (int rep = 0; rep < 8; rep++) {
            int p = rep * 256 + tid;
            int key = p >> 5;
            int c4 = (p & 31) << 2;
            *(float4*)(KVs + key * 128 + c4) =
                *(const float4*)(vb + (size_t)(kn0 + key) * EMB + h * HD + c4);
        }

        // p = exp(s - mnew); store transposed; rescale O; psum partials
#pragma unroll
        for (int i = 0; i < 4; i++) {
            int m = ty4 + i;
            float mn = mprev[m];
            float al = alph[m];
            float ps = 0.f;
#pragma unroll
            for (int j = 0; j < 4; j++) {
                float pv = __expf(s[i][j] - mn);
                ps += pv;
                Ps[(tx4 + j) * 64 + m] = pv;
            }
            red[m * 16 + tx] = ps;
#pragma unroll
            for (int j = 0; j < 8; j++) o[i][j] *= al;
        }
        __syncthreads();
        if (tid < 64) {
            float srow = 0.f;
#pragma unroll
            for (int t = 0; t < 16; t++) srow += red[tid * 16 + t];
            lsum[tid] = lsum[tid] * alph[tid] + srow;
        }

        // O += P V
#pragma unroll 2
        for (int kk = 0; kk < 64; kk++) {
            float4 pa = *(const float4*)(Ps + kk * 64 + ty4);
            float4 v0 = *(const float4*)(KVs + kk * 128 + tx8);
            float4 v1 = *(const float4*)(KVs + kk * 128 + tx8 + 4);
            float aa[4] = {pa.x, pa.y, pa.z, pa.w};
            float vv[8] = {v0.x, v0.y, v0.z, v0.w, v1.x, v1.y, v1.z, v1.w};
#pragma unroll
            for (int i = 0; i < 4; i++)
#pragma unroll
                for (int j = 0; j < 8; j++) o[i][j] += aa[i] * vv[j];
        }
    }
    __syncthreads();
#pragma unroll
    for (int i = 0; i < 4; i++) {
        int m = ty4 + i;
        float inv = 1.0f / lsum[m];
        float4 c0 = {o[i][0] * inv, o[i][1] * inv, o[i][2] * inv, o[i][3] * inv};
        float4 c1 = {o[i][4] * inv, o[i][5] * inv, o[i][6] * inv, o[i][7] * inv};
        float* op = ob + (size_t)(qr0 + m) * EMB + h * HD + tx8;
        *(float4*)op = c0;
        *(float4*)(op + 4) = c1;
    }
}

// ---------------- anchor-row top-k tile selection ----------------
// One block per (qt, h). Ranking key exp(tile_max - M) reproduces the reference
// tile_scores ordering (shared softmax denominator; masked tiles underflow to 0.0
// exactly on both sides). Strict-> scan = lax.top_k lower-index tie-break.
__global__ void topk_kernel(const float* __restrict__ qb, const float* __restrict__ kb,
                            float* __restrict__ oidx) {
    __shared__ __align__(16) float logits[SEQ];
    __shared__ __align__(16) float qrow[HD];
    __shared__ float redm[128];
    __shared__ float tsc[32];
    const int qt = blockIdx.x, h = blockIdx.y;
    const int tid = threadIdx.x;  // 128
    const int r = qt * 128 + 127;

    qrow[tid] = qb[(size_t)r * EMB + h * HD + tid];
    __syncthreads();

    const float scale = 0.08838834764831845f;
    const float4* q4 = (const float4*)qrow;
    for (int i = 0; i < 32; i++) {
        int j = i * 128 + tid;
        float lg = NEGV;
        if (j <= r) {
            const float4* k4 = (const float4*)(kb + (size_t)j * EMB + h * HD);
            float acc = 0.f;
#pragma unroll
            for (int d = 0; d < 32; d++) {
                float4 a = q4[d];
                float4 b = k4[d];
                acc += a.x * b.x + a.y * b.y + a.z * b.z + a.w * b.w;
            }
            lg = acc * scale;
        }
        logits[j] = lg;
    }
    __syncthreads();

    float lm = -1e38f;
    for (int i = tid; i < SEQ; i += 128) lm = fmaxf(lm, logits[i]);
    redm[tid] = lm;
    __syncthreads();
    for (int st = 64; st > 0; st >>= 1) {
        if (tid < st) redm[tid] = fmaxf(redm[tid], redm[tid + st]);
        __syncthreads();
    }
    float M = redm[0];
    if (tid < 32) {
        float tm = -1e38f;
        for (int jj = 0; jj < 128; jj++) tm = fmaxf(tm, logits[tid * 128 + jj]);
        tsc[tid] = __expf(tm - M);
    }
    __syncthreads();
    if (tid == 0) {
        unsigned used = 0;
#pragma unroll
        for (int k = 0; k < 8; k++) {
            int best = 0;
            float bv = -1.f;
            for (int i = 0; i < 32; i++) {
                if (!((used >> i) & 1u) && tsc[i] > bv) { bv = tsc[i]; best = i; }
            }
            used |= 1u << best;
            oidx[(h * 32 + qt) * 8 + k] = (float)best;
        }
    }
}

// ---------------- launch ----------------
extern "C" void kernel_launch(void* const* d_in, const int* in_sizes, int n_in,
                              void* d_out, int out_size) {
    const float* x    = (const float*)d_in[0];
    const float* wq   = (const float*)d_in[1];
    const float* wk   = (const float*)d_in[2];
    const float* wv   = (const float*)d_in[3];
    const float* wo   = (const float*)d_in[4];
    const float* cosb = (const float*)d_in[5];
    const float* sinb = (const float*)d_in[6];
    float* out = (float*)d_out;

    float *qp, *kp, *vp, *ap;
    cudaGetSymbolAddress((void**)&qp, g_q);
    cudaGetSymbolAddress((void**)&kp, g_k);
    cudaGetSymbolAddress((void**)&vp, g_v);
    cudaGetSymbolAddress((void**)&ap, g_attn);

    const int FSMEM = 86784;
    cudaFuncSetAttribute(flash_kernel, cudaFuncAttributeMaxDynamicSharedMemorySize, FSMEM);

    dim3 gg(SEQ / 128, EMB / 128);  // (32, 8)
    gemm_kernel<<<gg, 256>>>(x, wq, qp);
    gemm_kernel<<<gg, 256>>>(x, wk, kp);
    gemm_kernel<<<gg, 256>>>(x, wv, vp);

    rope_kernel<<<(2 * SEQ * NH * 64 + 255) / 256, 256>>>(cosb, sinb);

    flash_kernel<<<dim3(SEQ / 64, NH), 256, FSMEM>>>(qp, kp, vp, ap);

    // indices region: last H*32*8 = 2048 elements of the output buffer
    float* idx_out = out + (out_size - NH * 32 * 8);
    topk_kernel<<<dim3(32, NH), 128>>>(qp, kp, idx_out);

    gemm_kernel<<<gg, 256>>>(ap, wo, out);
}

// round 12
// speedup vs baseline: 1.2175x; 1.2175x over previous
#include <cuda_runtime.h>
#include <cuda_bf16.h>
#include <cstdint>

#define SEQ 4096
#define EMB 1024
#define NH  8
#define HD  128
#define NEGV -1e10f

// ---------------- scratch (no allocations allowed) ----------------
__device__ float g_q[SEQ * EMB];
__device__ float g_k[SEQ * EMB];
__device__ float g_v[SEQ * EMB];
__device__ float g_attn[SEQ * EMB];
__device__ __nv_bfloat16 g_xhi[SEQ * EMB];
__device__ __nv_bfloat16 g_xlo[SEQ * EMB];
__device__ __nv_bfloat16 g_wthi[EMB * EMB];
__device__ __nv_bfloat16 g_wtlo[EMB * EMB];

// ================= helpers (target-portable PTX only) =================
__device__ __forceinline__ uint32_t smem_u32(const void* p) {
    uint32_t a;
    asm("{ .reg .u64 t; cvta.to.shared.u64 t, %1; cvt.u32.u64 %0, t; }" : "=r"(a) : "l"(p));
    return a;
}
__device__ __forceinline__ void cpa16(uint32_t dst, const void* src) {
    asm volatile("cp.async.cg.shared.global [%0], [%1], 16;" :: "r"(dst), "l"(src) : "memory");
}
#define CP_COMMIT() asm volatile("cp.async.commit_group;" ::: "memory")
#define CP_WAIT1()  asm volatile("cp.async.wait_group 1;" ::: "memory")
#define CP_WAIT0()  asm volatile("cp.async.wait_group 0;" ::: "memory")

// mma.sync m16n8k16 bf16 -> f32 accumulate (valid on base sm_80+ targets)
__device__ __forceinline__ void mma16816(float* d, const uint32_t* a, const uint32_t* b) {
    asm volatile(
        "mma.sync.aligned.m16n8k16.row.col.f32.bf16.bf16.f32 "
        "{%0,%1,%2,%3}, {%4,%5,%6,%7}, {%8,%9}, {%0,%1,%2,%3};"
        : "+f"(d[0]), "+f"(d[1]), "+f"(d[2]), "+f"(d[3])
        : "r"(a[0]), "r"(a[1]), "r"(a[2]), "r"(a[3]), "r"(b[0]), "r"(b[1]));
}

// ================= split kernels =================
// fp32 -> (hi bf16, lo bf16), same layout. 1 thread = 4 elements.
__global__ void xsplit_kernel(const float* __restrict__ X, __nv_bfloat16* __restrict__ hi,
                              __nv_bfloat16* __restrict__ lo) {
    int i = blockIdx.x * 256 + threadIdx.x;  // over SEQ*EMB/4
    float4 v = ((const float4*)X)[i];
    __nv_bfloat16 h0 = __float2bfloat16(v.x), h1 = __float2bfloat16(v.y);
    __nv_bfloat16 h2 = __float2bfloat16(v.z), h3 = __float2bfloat16(v.w);
    __nv_bfloat16 l0 = __float2bfloat16(v.x - __bfloat162float(h0));
    __nv_bfloat16 l1 = __float2bfloat16(v.y - __bfloat162float(h1));
    __nv_bfloat16 l2 = __float2bfloat16(v.z - __bfloat162float(h2));
    __nv_bfloat16 l3 = __float2bfloat16(v.w - __bfloat162float(h3));
    __nv_bfloat162 H0; H0.x = h0; H0.y = h1;
    __nv_bfloat162 H1; H1.x = h2; H1.y = h3;
    __nv_bfloat162 L0; L0.x = l0; L0.y = l1;
    __nv_bfloat162 L1; L1.x = l2; L1.y = l3;
    ((__nv_bfloat162*)hi)[2 * i] = H0;
    ((__nv_bfloat162*)hi)[2 * i + 1] = H1;
    ((__nv_bfloat162*)lo)[2 * i] = L0;
    ((__nv_bfloat162*)lo)[2 * i + 1] = L1;
}

// W[k][n] fp32 -> WT hi/lo bf16 [n][k] (transpose + split), 32x32 SMEM tiles.
__global__ void wsplit_kernel(const float* __restrict__ W, __nv_bfloat16* __restrict__ hiT,
                              __nv_bfloat16* __restrict__ loT) {
    __shared__ float t[32][33];
    const int kb = blockIdx.x * 32, nb = blockIdx.y * 32;
    const int lx = threadIdx.x & 31, ly = threadIdx.x >> 5;  // 256 thr
#pragma unroll
    for (int r = ly; r < 32; r += 8)
        t[r][lx] = W[(size_t)(kb + r) * EMB + nb + lx];
    __syncthreads();
#pragma unroll
    for (int r = ly; r < 32; r += 8) {
        float v = t[lx][r];  // = W[kb+lx][nb+r]
        __nv_bfloat16 h = __float2bfloat16(v);
        __nv_bfloat16 l = __float2bfloat16(v - __bfloat162float(h));
        hiT[(size_t)(nb + r) * EMB + kb + lx] = h;
        loT[(size_t)(nb + r) * EMB + kb + lx] = l;
    }
}

// ================= HMMA GEMM =================
// C[4096,1024] = X @ W, pre-split bf16: Ah/Al [M][K] k-major, Bh/Bl [N][K] k-major.
// D += Ah*Bh + Ah*Bl + Al*Bh  (3-term split-bf16, residual ~2^-16).
// CTA 128x128, K-chunk 64, cp.async double buffer, 8 warps: 4(m) x 2(n), warp tile 32x64.
// SMEM rows padded to 144B -> conflict-free fragment loads.
#define KC 64
#define NCHUNK (EMB / KC)
#define ROWB 144                     // 72 bf16 per padded row
#define TILEB (128 * ROWB)           // 18432 B per operand tile
#define STAGEB (4 * TILEB)           // 73728 B per stage
#define GSMEM (2 * STAGEB)           // 147456 B

__global__ __launch_bounds__(256, 1) void gemm_mma_kernel(
    const __nv_bfloat16* __restrict__ Ah, const __nv_bfloat16* __restrict__ Al,
    const __nv_bfloat16* __restrict__ Bh, const __nv_bfloat16* __restrict__ Bl,
    float* __restrict__ C) {
    extern __shared__ __align__(16) char sm[];
    const int tid = threadIdx.x;
    const int wid = tid >> 5, lane = tid & 31;
    const int bm = blockIdx.x * 128, bn = blockIdx.y * 128;
    const int wm = (wid & 3) * 32, wn = (wid >> 2) * 64;
    const int lr = lane >> 2, lc2 = (lane & 3) * 2;  // frag row-in-8, k/n pair col
    const uint32_t smb = smem_u32(sm);

    float acc[2][8][4];
#pragma unroll
    for (int mt = 0; mt < 2; mt++)
#pragma unroll
        for (int nt = 0; nt < 8; nt++)
#pragma unroll
            for (int e = 0; e < 4; e++) acc[mt][nt][e] = 0.f;

    // ---- async stage loader: 4 operand tiles, 128 rows x 64 bf16 each ----
    auto issue = [&](int c) {
        const uint32_t sb = smb + (uint32_t)(c & 1) * STAGEB;
        const size_t koff = (size_t)c * KC;
#pragma unroll
        for (int i = 0; i < 4; i++) {
            int f = tid + i * 256;          // 0..1023
            int r = f >> 3, seg = f & 7;    // row, 16B segment
            uint32_t so = (uint32_t)(r * ROWB + seg * 16);
            const size_t ga = (size_t)(bm + r) * EMB + koff + seg * 8;
            const size_t gb = (size_t)(bn + r) * EMB + koff + seg * 8;
            cpa16(sb + 0 * TILEB + so, Ah + ga);
            cpa16(sb + 1 * TILEB + so, Al + ga);
            cpa16(sb + 2 * TILEB + so, Bh + gb);
            cpa16(sb + 3 * TILEB + so, Bl + gb);
        }
        CP_COMMIT();
    };

    issue(0);
    for (int c = 0; c < NCHUNK; c++) {
        if (c + 1 < NCHUNK) { issue(c + 1); CP_WAIT1(); }
        else                { CP_WAIT0(); }
        __syncthreads();

        const char* st = sm + (c & 1) * STAGEB;
        const char* pAh = st;
        const char* pAl = st + TILEB;
        const char* pBh = st + 2 * TILEB;
        const char* pBl = st + 3 * TILEB;

#pragma unroll
        for (int ks = 0; ks < 4; ks++) {
            const int k0 = ks * 16;
            // A fragments: a0=(r,k) a1=(r+8,k) a2=(r,k+8) a3=(r+8,k+8)
            uint32_t ah[2][4], al[2][4];
#pragma unroll
            for (int mt = 0; mt < 2; mt++) {
                int row = wm + mt * 16 + lr;
                const char* a0 = pAh + row * ROWB + (k0 + lc2) * 2;
                ah[mt][0] = *(const uint32_t*)(a0);
                ah[mt][1] = *(const uint32_t*)(a0 + 8 * ROWB);
                ah[mt][2] = *(const uint32_t*)(a0 + 16);
                ah[mt][3] = *(const uint32_t*)(a0 + 8 * ROWB + 16);
                const char* a1 = pAl + row * ROWB + (k0 + lc2) * 2;
                al[mt][0] = *(const uint32_t*)(a1);
                al[mt][1] = *(const uint32_t*)(a1 + 8 * ROWB);
                al[mt][2] = *(const uint32_t*)(a1 + 16);
                al[mt][3] = *(const uint32_t*)(a1 + 8 * ROWB + 16);
            }
#pragma unroll
            for (int nt = 0; nt < 8; nt++) {
                // B fragment: b0=(k=lc2..,n=lr) b1=(k+8,n=lr); B stored [n][k]
                int n = wn + nt * 8 + lr;
                const char* b0 = pBh + n * ROWB + (k0 + lc2) * 2;
                uint32_t bh[2] = {*(const uint32_t*)(b0), *(const uint32_t*)(b0 + 16)};
                const char* b1 = pBl + n * ROWB + (k0 + lc2) * 2;
                uint32_t bl[2] = {*(const uint32_t*)(b1), *(const uint32_t*)(b1 + 16)};
#pragma unroll
                for (int mt = 0; mt < 2; mt++) {
                    mma16816(acc[mt][nt], ah[mt], bh);
                    mma16816(acc[mt][nt], ah[mt], bl);
                    mma16816(acc[mt][nt], al[mt], bh);
                }
            }
        }
        __syncthreads();
    }

    // ---- epilogue: c0,c1 = (m=lr, n=lc2..), c2,c3 = (m=lr+8, n=lc2..) ----
#pragma unroll
    for (int mt = 0; mt < 2; mt++) {
#pragma unroll
        for (int nt = 0; nt < 8; nt++) {
            int row = bm + wm + mt * 16 + lr;
            int col = bn + wn + nt * 8 + lc2;
            float2 v0 = {acc[mt][nt][0], acc[mt][nt][1]};
            float2 v1 = {acc[mt][nt][2], acc[mt][nt][3]};
            *(float2*)(C + (size_t)row * EMB + col) = v0;
            *(float2*)(C + (size_t)(row + 8) * EMB + col) = v1;
        }
    }
}

// ---------------- RoPE in-place on g_q, g_k ----------------
__global__ void rope_kernel(const float* __restrict__ cosb, const float* __restrict__ sinb) {
    int idx = blockIdx.x * blockDim.x + threadIdx.x;
    if (idx >= 2 * SEQ * NH * 64) return;
    int t = idx >> 21;
    int rem = idx & 2097151;
    int s = rem >> 9;
    int r2 = rem & 511;
    int h = r2 >> 6;
    int d = r2 & 63;
    float* p = t ? g_k : g_q;
    int base = s * EMB + h * HD + d;
    float a = p[base];
    float b = p[base + 64];
    float c = cosb[s * 64 + d];
    float sn = sinb[s * 64 + d];
    p[base] = a * c - b * sn;
    p[base + 64] = b * c + a * sn;
}

// ---------------- causal flash attention, fp32, BM=BN=64 ----------------
__global__ __launch_bounds__(256, 2) void flash_kernel(const float* __restrict__ qb,
                                                       const float* __restrict__ kb,
                                                       const float* __restrict__ vb,
                                                       float* __restrict__ ob) {
    extern __shared__ __align__(16) float fsm[];
    float* Qs  = fsm;
    float* KVs = fsm + 8192;
    float* Ps  = fsm + 16384;
    float* red = fsm + 20480;
    float* mprev = fsm + 21504;
    float* lsum  = fsm + 21568;
    float* alph  = fsm + 21632;

    const int tid = threadIdx.x;
    const int qbk = (int)gridDim.x - 1 - (int)blockIdx.x;
    const int h = blockIdx.y;
    const int qr0 = qbk * 64;
    const int ty = tid >> 4, tx = tid & 15;
    const int ty4 = ty * 4, tx4 = tx * 4, tx8 = tx * 8;
    const float scale = 0.08838834764831845f;

#pragma unroll
    for (int rep = 0; rep < 8; rep++) {
        int p = rep * 256 + tid;
        int r = p >> 5;
        int kk4 = (p & 31) << 2;
        float4 v = *(const float4*)(qb + (size_t)(qr0 + r) * EMB + h * HD + kk4);
        Qs[(kk4 + 0) * 64 + r] = v.x * scale;
        Qs[(kk4 + 1) * 64 + r] = v.y * scale;
        Qs[(kk4 + 2) * 64 + r] = v.z * scale;
        Qs[(kk4 + 3) * 64 + r] = v.w * scale;
    }
    if (tid < 64) { mprev[tid] = -1e30f; lsum[tid] = 0.f; }

    float o[4][8];
#pragma unroll
    for (int i = 0; i < 4; i++)
#pragma unroll
        for (int j = 0; j < 8; j++) o[i][j] = 0.f;

    for (int kt = 0; kt <= qbk; kt++) {
        const int kn0 = kt * 64;
        __syncthreads();
#pragma unroll
        for (int rep = 0; rep < 8; rep++) {
            int p = rep * 256 + tid;
            int n = p >> 5;
            int kk4 = (p & 31) << 2;
            float4 v = *(const float4*)(kb + (size_t)(kn0 + n) * EMB + h * HD + kk4);
            KVs[(kk4 + 0) * 64 + n] = v.x;
            KVs[(kk4 + 1) * 64 + n] = v.y;
            KVs[(kk4 + 2) * 64 + n] = v.z;
            KVs[(kk4 + 3) * 64 + n] = v.w;
        }
        __syncthreads();

        float s[4][4];
#pragma unroll
        for (int i = 0; i < 4; i++)
#pragma unroll
            for (int j = 0; j < 4; j++) s[i][j] = 0.f;
#pragma unroll 4
        for (int kk = 0; kk < 128; kk++) {
            float4 a = *(const float4*)(Qs + kk * 64 + ty4);
            float4 b = *(const float4*)(KVs + kk * 64 + tx4);
            float aa[4] = {a.x, a.y, a.z, a.w};
            float bb[4] = {b.x, b.y, b.z, b.w};
#pragma unroll
            for (int i = 0; i < 4; i++)
#pragma unroll
                for (int j = 0; j < 4; j++) s[i][j] += aa[i] * bb[j];
        }

        if (kt == qbk) {
#pragma unroll
            for (int i = 0; i < 4; i++)
#pragma unroll
                for (int j = 0; j < 4; j++)
                    if (tx4 + j > ty4 + i) s[i][j] = -1e30f;
        }

#pragma unroll
        for (int i = 0; i < 4; i++) {
            float pm = fmaxf(fmaxf(s[i][0], s[i][1]), fmaxf(s[i][2], s[i][3]));
            red[(ty4 + i) * 16 + tx] = pm;
        }
        __syncthreads();
        if (tid < 64) {
            float mrow = red[tid * 16];
#pragma unroll
            for (int t = 1; t < 16; t++) mrow = fmaxf(mrow, red[tid * 16 + t]);
            float mold = mprev[tid];
            float mnew = fmaxf(mold, mrow);
            mprev[tid] = mnew;
            alph[tid] = __expf(mold - mnew);
        }
        __syncthreads();

#pragma unroll
        for (int rep = 0; rep < 8; rep++) {
            int p = rep * 256 + tid;
            int key = p >> 5;
            int c4 = (p & 31) << 2;
            *(float4*)(KVs + key * 128 + c4) =
                *(const float4*)(vb + (size_t)(kn0 + key) * EMB + h * HD + c4);
        }

#pragma unroll
        for (int i = 0; i < 4; i++) {
            int m = ty4 + i;
            float mn = mprev[m];
            float al = alph[m];
            float ps = 0.f;
#pragma unroll
            for (int j = 0; j < 4; j++) {
                float pv = __expf(s[i][j] - mn);
                ps += pv;
                Ps[(tx4 + j) * 64 + m] = pv;
            }
            red[m * 16 + tx] = ps;
#pragma unroll
            for (int j = 0; j < 8; j++) o[i][j] *= al;
        }
        __syncthreads();
        if (tid < 64) {
            float srow = 0.f;
#pragma unroll
            for (int t = 0; t < 16; t++) srow += red[tid * 16 + t];
            lsum[tid] = lsum[tid] * alph[tid] + srow;
        }

#pragma unroll 2
        for (int kk = 0; kk < 64; kk++) {
            float4 pa = *(const float4*)(Ps + kk * 64 + ty4);
            float4 v0 = *(const float4*)(KVs + kk * 128 + tx8);
            float4 v1 = *(const float4*)(KVs + kk * 128 + tx8 + 4);
            float aa[4] = {pa.x, pa.y, pa.z, pa.w};
            float vv[8] = {v0.x, v0.y, v0.z, v0.w, v1.x, v1.y, v1.z, v1.w};
#pragma unroll
            for (int i = 0; i < 4; i++)
#pragma unroll
                for (int j = 0; j < 8; j++) o[i][j] += aa[i] * vv[j];
        }
    }
    __syncthreads();
#pragma unroll
    for (int i = 0; i < 4; i++) {
        int m = ty4 + i;
        float inv = 1.0f / lsum[m];
        float4 c0 = {o[i][0] * inv, o[i][1] * inv, o[i][2] * inv, o[i][3] * inv};
        float4 c1 = {o[i][4] * inv, o[i][5] * inv, o[i][6] * inv, o[i][7] * inv};
        float* op = ob + (size_t)(qr0 + m) * EMB + h * HD + tx8;
        *(float4*)op = c0;
        *(float4*)(op + 4) = c1;
    }
}

// ---------------- anchor-row top-k tile selection ----------------
__global__ void topk_kernel(const float* __restrict__ qb, const float* __restrict__ kb,
                            float* __restrict__ oidx) {
    __shared__ __align__(16) float logits[SEQ];
    __shared__ __align__(16) float qrow[HD];
    __shared__ float redm[128];
    __shared__ float tsc[32];
    const int qt = blockIdx.x, h = blockIdx.y;
    const int tid = threadIdx.x;
    const int r = qt * 128 + 127;

    qrow[tid] = qb[(size_t)r * EMB + h * HD + tid];
    __syncthreads();

    const float scale = 0.08838834764831845f;
    const float4* q4 = (const float4*)qrow;
    for (int i = 0; i < 32; i++) {
        int j = i * 128 + tid;
        float lg = NEGV;
        if (j <= r) {
            const float4* k4 = (const float4*)(kb + (size_t)j * EMB + h * HD);
            float acc = 0.f;
#pragma unroll
            for (int d = 0; d < 32; d++) {
                float4 a = q4[d];
                float4 b = k4[d];
                acc += a.x * b.x + a.y * b.y + a.z * b.z + a.w * b.w;
            }
            lg = acc * scale;
        }
        logits[j] = lg;
    }
    __syncthreads();

    float lm = -1e38f;
    for (int i = tid; i < SEQ; i += 128) lm = fmaxf(lm, logits[i]);
    redm[tid] = lm;
    __syncthreads();
    for (int st = 64; st > 0; st >>= 1) {
        if (tid < st) redm[tid] = fmaxf(redm[tid], redm[tid + st]);
        __syncthreads();
    }
    float M = redm[0];
    if (tid < 32) {
        float tm = -1e38f;
        for (int jj = 0; jj < 128; jj++) tm = fmaxf(tm, logits[tid * 128 + jj]);
        tsc[tid] = __expf(tm - M);
    }
    __syncthreads();
    if (tid == 0) {
        unsigned used = 0;
#pragma unroll
        for (int k = 0; k < 8; k++) {
            int best = 0;
            float bv = -1.f;
            for (int i = 0; i < 32; i++) {
                if (!((used >> i) & 1u) && tsc[i] > bv) { bv = tsc[i]; best = i; }
            }
            used |= 1u << best;
            oidx[(h * 32 + qt) * 8 + k] = (float)best;
        }
    }
}

// ---------------- launch ----------------
extern "C" void kernel_launch(void* const* d_in, const int* in_sizes, int n_in,
                              void* d_out, int out_size) {
    const float* x    = (const float*)d_in[0];
    const float* wq   = (const float*)d_in[1];
    const float* wk   = (const float*)d_in[2];
    const float* wv   = (const float*)d_in[3];
    const float* wo   = (const float*)d_in[4];
    const float* cosb = (const float*)d_in[5];
    const float* sinb = (const float*)d_in[6];
    float* out = (float*)d_out;

    float *qp, *kp, *vp, *ap;
    __nv_bfloat16 *xhi, *xlo, *wthi, *wtlo;
    cudaGetSymbolAddress((void**)&qp, g_q);
    cudaGetSymbolAddress((void**)&kp, g_k);
    cudaGetSymbolAddress((void**)&vp, g_v);
    cudaGetSymbolAddress((void**)&ap, g_attn);
    cudaGetSymbolAddress((void**)&xhi, g_xhi);
    cudaGetSymbolAddress((void**)&xlo, g_xlo);
    cudaGetSymbolAddress((void**)&wthi, g_wthi);
    cudaGetSymbolAddress((void**)&wtlo, g_wtlo);

    const int FSMEM = 86784;
    cudaFuncSetAttribute(flash_kernel, cudaFuncAttributeMaxDynamicSharedMemorySize, FSMEM);
    cudaFuncSetAttribute(gemm_mma_kernel, cudaFuncAttributeMaxDynamicSharedMemorySize, GSMEM);

    dim3 gg(SEQ / 128, EMB / 128);  // (32, 8)
    dim3 wg(EMB / 32, EMB / 32);    // (32, 32)

    xsplit_kernel<<<SEQ * EMB / 4 / 256, 256>>>(x, xhi, xlo);

    wsplit_kernel<<<wg, 256>>>(wq, wthi, wtlo);
    gemm_mma_kernel<<<gg, 256, GSMEM>>>(xhi, xlo, wthi, wtlo, qp);
    wsplit_kernel<<<wg, 256>>>(wk, wthi, wtlo);
    gemm_mma_kernel<<<gg, 256, GSMEM>>>(xhi, xlo, wthi, wtlo, kp);
    wsplit_kernel<<<wg, 256>>>(wv, wthi, wtlo);
    gemm_mma_kernel<<<gg, 256, GSMEM>>>(xhi, xlo, wthi, wtlo, vp);

    rope_kernel<<<(2 * SEQ * NH * 64 + 255) / 256, 256>>>(cosb, sinb);

    flash_kernel<<<dim3(SEQ / 64, NH), 256, FSMEM>>>(qp, kp, vp, ap);

    float* idx_out = out + (out_size - NH * 32 * 8);
    topk_kernel<<<dim3(32, NH), 128>>>(qp, kp, idx_out);

    xsplit_kernel<<<SEQ * EMB / 4 / 256, 256>>>(ap, xhi, xlo);
    wsplit_kernel<<<wg, 256>>>(wo, wthi, wtlo);
    gemm_mma_kernel<<<gg, 256, GSMEM>>>(xhi, xlo, wthi, wtlo, out);
}

// round 13
// speedup vs baseline: 3.3636x; 2.7628x over previous
#include <cuda_runtime.h>
#include <cuda_bf16.h>
#include <cstdint>

#define SEQ 4096
#define EMB 1024
#define NH  8
#define HD  128
#define NEGV -1e10f

// ---------------- scratch (no allocations allowed) ----------------
__device__ float g_q[SEQ * EMB];
__device__ float g_k[SEQ * EMB];
__device__ float g_v[SEQ * EMB];
__device__ float g_attn[SEQ * EMB];
__device__ __nv_bfloat16 g_xhi[SEQ * EMB];
__device__ __nv_bfloat16 g_xlo[SEQ * EMB];
__device__ __nv_bfloat16 g_wthi[EMB * EMB];
__device__ __nv_bfloat16 g_wtlo[EMB * EMB];
__device__ __nv_bfloat16 g_qh[SEQ * EMB];
__device__ __nv_bfloat16 g_ql[SEQ * EMB];
__device__ __nv_bfloat16 g_kh[SEQ * EMB];
__device__ __nv_bfloat16 g_kl[SEQ * EMB];
__device__ __nv_bfloat16 g_vth[EMB * SEQ];  // [h*HD+d][s]
__device__ __nv_bfloat16 g_vtl[EMB * SEQ];

// ================= helpers (target-portable PTX only) =================
__device__ __forceinline__ uint32_t smem_u32(const void* p) {
    uint32_t a;
    asm("{ .reg .u64 t; cvta.to.shared.u64 t, %1; cvt.u32.u64 %0, t; }" : "=r"(a) : "l"(p));
    return a;
}
__device__ __forceinline__ void cpa16(uint32_t dst, const void* src) {
    asm volatile("cp.async.cg.shared.global [%0], [%1], 16;" :: "r"(dst), "l"(src) : "memory");
}
#define CP_COMMIT() asm volatile("cp.async.commit_group;" ::: "memory")
#define CP_WAIT1()  asm volatile("cp.async.wait_group 1;" ::: "memory")
#define CP_WAIT0()  asm volatile("cp.async.wait_group 0;" ::: "memory")

// mma.sync m16n8k16 bf16 -> f32 accumulate (valid on base sm_80+ targets)
__device__ __forceinline__ void mma16816(float* d, const uint32_t* a, const uint32_t* b) {
    asm volatile(
        "mma.sync.aligned.m16n8k16.row.col.f32.bf16.bf16.f32 "
        "{%0,%1,%2,%3}, {%4,%5,%6,%7}, {%8,%9}, {%0,%1,%2,%3};"
        : "+f"(d[0]), "+f"(d[1]), "+f"(d[2]), "+f"(d[3])
        : "r"(a[0]), "r"(a[1]), "r"(a[2]), "r"(a[3]), "r"(b[0]), "r"(b[1]));
}

// pack two floats to bf16x2 (lo=a, hi=b), return residuals
__device__ __forceinline__ uint32_t packbf(float a, float b, float& ra, float& rb) {
    __nv_bfloat162 t;
    t.x = __float2bfloat16(a);
    t.y = __float2bfloat16(b);
    ra = a - __bfloat162float(t.x);
    rb = b - __bfloat162float(t.y);
    return *(uint32_t*)&t;
}
__device__ __forceinline__ uint32_t packbf2(float a, float b) {
    __nv_bfloat162 t;
    t.x = __float2bfloat16(a);
    t.y = __float2bfloat16(b);
    return *(uint32_t*)&t;
}

// ================= split kernels =================
__global__ void xsplit_kernel(const float* __restrict__ X, __nv_bfloat16* __restrict__ hi,
                              __nv_bfloat16* __restrict__ lo) {
    int i = blockIdx.x * 256 + threadIdx.x;  // over SEQ*EMB/4
    float4 v = ((const float4*)X)[i];
    float r0, r1, r2, r3;
    uint32_t h0 = packbf(v.x, v.y, r0, r1);
    uint32_t h1 = packbf(v.z, v.w, r2, r3);
    ((uint32_t*)hi)[2 * i] = h0;
    ((uint32_t*)hi)[2 * i + 1] = h1;
    ((uint32_t*)lo)[2 * i] = packbf2(r0, r1);
    ((uint32_t*)lo)[2 * i + 1] = packbf2(r2, r3);
}

// W[k][n] fp32 -> WT hi/lo bf16 [n][k] (transpose + split), 32x32 SMEM tiles.
__global__ void wsplit_kernel(const float* __restrict__ W, __nv_bfloat16* __restrict__ hiT,
                              __nv_bfloat16* __restrict__ loT) {
    __shared__ float t[32][33];
    const int kb = blockIdx.x * 32, nb = blockIdx.y * 32;
    const int lx = threadIdx.x & 31, ly = threadIdx.x >> 5;  // 256 thr
#pragma unroll
    for (int r = ly; r < 32; r += 8)
        t[r][lx] = W[(size_t)(kb + r) * EMB + nb + lx];
    __syncthreads();
#pragma unroll
    for (int r = ly; r < 32; r += 8) {
        float v = t[lx][r];
        __nv_bfloat16 h = __float2bfloat16(v);
        __nv_bfloat16 l = __float2bfloat16(v - __bfloat162float(h));
        hiT[(size_t)(nb + r) * EMB + kb + lx] = h;
        loT[(size_t)(nb + r) * EMB + kb + lx] = l;
    }
}

// q (scaled by 1/sqrt(D)) and k -> bf16 hi/lo splits, same [S][E] layout
__global__ void qksplit_kernel(__nv_bfloat16* __restrict__ qh, __nv_bfloat16* __restrict__ ql,
                               __nv_bfloat16* __restrict__ kh, __nv_bfloat16* __restrict__ kl) {
    int idx = blockIdx.x * 256 + threadIdx.x;  // 2 * SEQ*EMB/4 threads
    int t = idx >> 20;                         // SEQ*EMB/4 = 2^20
    int i = idx & ((1 << 20) - 1);
    const float* src = t ? g_k : g_q;
    const float sc = t ? 1.0f : 0.08838834764831845f;
    float4 v = ((const float4*)src)[i];
    v.x *= sc; v.y *= sc; v.z *= sc; v.w *= sc;
    __nv_bfloat16* hi = t ? kh : qh;
    __nv_bfloat16* lo = t ? kl : ql;
    float r0, r1, r2, r3;
    uint32_t h0 = packbf(v.x, v.y, r0, r1);
    uint32_t h1 = packbf(v.z, v.w, r2, r3);
    ((uint32_t*)hi)[2 * i] = h0;
    ((uint32_t*)hi)[2 * i + 1] = h1;
    ((uint32_t*)lo)[2 * i] = packbf2(r0, r1);
    ((uint32_t*)lo)[2 * i + 1] = packbf2(r2, r3);
}

// V [s][h*HD+d] fp32 -> Vt hi/lo bf16 [h*HD+d][s]
__global__ void vtsplit_kernel(const float* __restrict__ V, __nv_bfloat16* __restrict__ vth,
                               __nv_bfloat16* __restrict__ vtl) {
    __shared__ float t[32][33];
    const int sb = blockIdx.x * 32, db = blockIdx.y * 32, h = blockIdx.z;
    const int lx = threadIdx.x & 31, ly = threadIdx.x >> 5;  // 256 thr
#pragma unroll
    for (int r = ly; r < 32; r += 8)
        t[r][lx] = V[(size_t)(sb + r) * EMB + h * HD + db + lx];
    __syncthreads();
#pragma unroll
    for (int r = ly; r < 32; r += 8) {
        float v = t[lx][r];  // V[s=sb+lx][d=db+r]
        __nv_bfloat16 hh = __float2bfloat16(v);
        __nv_bfloat16 ll = __float2bfloat16(v - __bfloat162float(hh));
        vth[(size_t)(h * HD + db + r) * SEQ + sb + lx] = hh;
        vtl[(size_t)(h * HD + db + r) * SEQ + sb + lx] = ll;
    }
}

// ================= HMMA GEMM (unchanged from R12, passing) =================
#define KC 64
#define NCHUNK (EMB / KC)
#define ROWB 144
#define TILEB (128 * ROWB)
#define STAGEB (4 * TILEB)
#define GSMEM (2 * STAGEB)

__global__ __launch_bounds__(256, 1) void gemm_mma_kernel(
    const __nv_bfloat16* __restrict__ Ah, const __nv_bfloat16* __restrict__ Al,
    const __nv_bfloat16* __restrict__ Bh, const __nv_bfloat16* __restrict__ Bl,
    float* __restrict__ C) {
    extern __shared__ __align__(16) char sm[];
    const int tid = threadIdx.x;
    const int wid = tid >> 5, lane = tid & 31;
    const int bm = blockIdx.x * 128, bn = blockIdx.y * 128;
    const int wm = (wid & 3) * 32, wn = (wid >> 2) * 64;
    const int lr = lane >> 2, lc2 = (lane & 3) * 2;
    const uint32_t smb = smem_u32(sm);

    float acc[2][8][4];
#pragma unroll
    for (int mt = 0; mt < 2; mt++)
#pragma unroll
        for (int nt = 0; nt < 8; nt++)
#pragma unroll
            for (int e = 0; e < 4; e++) acc[mt][nt][e] = 0.f;

    auto issue = [&](int c) {
        const uint32_t sb = smb + (uint32_t)(c & 1) * STAGEB;
        const size_t koff = (size_t)c * KC;
#pragma unroll
        for (int i = 0; i < 4; i++) {
            int f = tid + i * 256;
            int r = f >> 3, seg = f & 7;
            uint32_t so = (uint32_t)(r * ROWB + seg * 16);
            const size_t ga = (size_t)(bm + r) * EMB + koff + seg * 8;
            const size_t gb = (size_t)(bn + r) * EMB + koff + seg * 8;
            cpa16(sb + 0 * TILEB + so, Ah + ga);
            cpa16(sb + 1 * TILEB + so, Al + ga);
            cpa16(sb + 2 * TILEB + so, Bh + gb);
            cpa16(sb + 3 * TILEB + so, Bl + gb);
        }
        CP_COMMIT();
    };

    issue(0);
    for (int c = 0; c < NCHUNK; c++) {
        if (c + 1 < NCHUNK) { issue(c + 1); CP_WAIT1(); }
        else                { CP_WAIT0(); }
        __syncthreads();

        const char* st = sm + (c & 1) * STAGEB;
        const char* pAh = st;
        const char* pAl = st + TILEB;
        const char* pBh = st + 2 * TILEB;
        const char* pBl = st + 3 * TILEB;

#pragma unroll
        for (int ks = 0; ks < 4; ks++) {
            const int k0 = ks * 16;
            uint32_t ah[2][4], al[2][4];
#pragma unroll
            for (int mt = 0; mt < 2; mt++) {
                int row = wm + mt * 16 + lr;
                const char* a0 = pAh + row * ROWB + (k0 + lc2) * 2;
                ah[mt][0] = *(const uint32_t*)(a0);
                ah[mt][1] = *(const uint32_t*)(a0 + 8 * ROWB);
                ah[mt][2] = *(const uint32_t*)(a0 + 16);
                ah[mt][3] = *(const uint32_t*)(a0 + 8 * ROWB + 16);
                const char* a1 = pAl + row * ROWB + (k0 + lc2) * 2;
                al[mt][0] = *(const uint32_t*)(a1);
                al[mt][1] = *(const uint32_t*)(a1 + 8 * ROWB);
                al[mt][2] = *(const uint32_t*)(a1 + 16);
                al[mt][3] = *(const uint32_t*)(a1 + 8 * ROWB + 16);
            }
#pragma unroll
            for (int nt = 0; nt < 8; nt++) {
                int n = wn + nt * 8 + lr;
                const char* b0 = pBh + n * ROWB + (k0 + lc2) * 2;
                uint32_t bh[2] = {*(const uint32_t*)(b0), *(const uint32_t*)(b0 + 16)};
                const char* b1 = pBl + n * ROWB + (k0 + lc2) * 2;
                uint32_t bl[2] = {*(const uint32_t*)(b1), *(const uint32_t*)(b1 + 16)};
#pragma unroll
                for (int mt = 0; mt < 2; mt++) {
                    mma16816(acc[mt][nt], ah[mt], bh);
                    mma16816(acc[mt][nt], ah[mt], bl);
                    mma16816(acc[mt][nt], al[mt], bh);
                }
            }
        }
        __syncthreads();
    }

#pragma unroll
    for (int mt = 0; mt < 2; mt++) {
#pragma unroll
        for (int nt = 0; nt < 8; nt++) {
            int row = bm + wm + mt * 16 + lr;
            int col = bn + wn + nt * 8 + lc2;
            float2 v0 = {acc[mt][nt][0], acc[mt][nt][1]};
            float2 v1 = {acc[mt][nt][2], acc[mt][nt][3]};
            *(float2*)(C + (size_t)row * EMB + col) = v0;
            *(float2*)(C + (size_t)(row + 8) * EMB + col) = v1;
        }
    }
}

// ---------------- RoPE in-place on g_q, g_k ----------------
__global__ void rope_kernel(const float* __restrict__ cosb, const float* __restrict__ sinb) {
    int idx = blockIdx.x * blockDim.x + threadIdx.x;
    if (idx >= 2 * SEQ * NH * 64) return;
    int t = idx >> 21;
    int rem = idx & 2097151;
    int s = rem >> 9;
    int r2 = rem & 511;
    int h = r2 >> 6;
    int d = r2 & 63;
    float* p = t ? g_k : g_q;
    int base = s * EMB + h * HD + d;
    float a = p[base];
    float b = p[base + 64];
    float c = cosb[s * 64 + d];
    float sn = sinb[s * 64 + d];
    p[base] = a * c - b * sn;
    p[base + 64] = b * c + a * sn;
}

// ================= HMMA causal flash attention =================
// BM=BN=64, 128 threads (4 warps x 16 rows). Q pre-scaled bf16 hi/lo in SMEM,
// K bf16 hi/lo, V transposed bf16 hi/lo. 3-term split MMA for S and PV.
#define QKROW 272   // 128 bf16 (256B) padded to 272 -> stride = 4 banks mod 32
#define VROW  144   // 64 bf16 (128B) padded to 144
#define SQH 0
#define SQL 17408
#define SKH 34816
#define SKL 52224
#define SVH 69632
#define SVL 88064
#define FSMEM 106496

__global__ __launch_bounds__(128, 2) void flash_hmma_kernel(
    const __nv_bfloat16* __restrict__ qh_, const __nv_bfloat16* __restrict__ ql_,
    const __nv_bfloat16* __restrict__ kh_, const __nv_bfloat16* __restrict__ kl_,
    const __nv_bfloat16* __restrict__ vth_, const __nv_bfloat16* __restrict__ vtl_,
    float* __restrict__ ob) {
    extern __shared__ __align__(16) char sm[];
    const int tid = threadIdx.x;
    const int wid = tid >> 5, lane = tid & 31;
    const int gr = lane >> 2, lc2 = (lane & 3) * 2;
    const int qbk = (int)gridDim.x - 1 - (int)blockIdx.x;  // longest first
    const int h = blockIdx.y;
    const int qr0 = qbk * 64;
    const int wm = wid * 16;
    const uint32_t smb = smem_u32(sm);

    // Q tile load (64 rows x 256B each buffer)
#pragma unroll
    for (int i = 0; i < 8; i++) {
        int f = i * 128 + tid;
        int r = f >> 4, seg = f & 15;
        const size_t g = (size_t)(qr0 + r) * EMB + h * HD + seg * 8;
        cpa16(smb + SQH + r * QKROW + seg * 16, qh_ + g);
        cpa16(smb + SQL + r * QKROW + seg * 16, ql_ + g);
    }
    CP_COMMIT();

    float o[16][4];
#pragma unroll
    for (int n = 0; n < 16; n++)
#pragma unroll
        for (int e = 0; e < 4; e++) o[n][e] = 0.f;
    float l0 = 0.f, l1 = 0.f, m0 = -1e30f, m1 = -1e30f;

    const char* Qh = sm + SQH;
    const char* Ql = sm + SQL;
    const char* Kh = sm + SKH;
    const char* Kl = sm + SKL;
    const char* Vh = sm + SVH;
    const char* Vl = sm + SVL;

    for (int kt = 0; kt <= qbk; kt++) {
        const int kn0 = kt * 64;
        __syncthreads();  // prior PV reads of K/V done
        // K tile: 64 rows x 256B; V tile: 128 rows x 128B
#pragma unroll
        for (int i = 0; i < 8; i++) {
            int f = i * 128 + tid;
            int r = f >> 4, seg = f & 15;
            const size_t g = (size_t)(kn0 + r) * EMB + h * HD + seg * 8;
            cpa16(smb + SKH + r * QKROW + seg * 16, kh_ + g);
            cpa16(smb + SKL + r * QKROW + seg * 16, kl_ + g);
            int rv = f >> 3, sv = f & 7;
            const size_t gv = (size_t)(h * HD + rv) * SEQ + kn0 + sv * 8;
            cpa16(smb + SVH + rv * VROW + sv * 16, vth_ + gv);
            cpa16(smb + SVL + rv * VROW + sv * 16, vtl_ + gv);
        }
        CP_COMMIT();
        CP_WAIT0();
        __syncthreads();

        // ---- S = Q K^T (scaled), 3-term split ----
        float s[8][4];
#pragma unroll
        for (int nt = 0; nt < 8; nt++)
#pragma unroll
            for (int e = 0; e < 4; e++) s[nt][e] = 0.f;
#pragma unroll
        for (int ks = 0; ks < 8; ks++) {
            const int k0 = ks * 16;
            const char* aq = Qh + (wm + gr) * QKROW + (k0 + lc2) * 2;
            uint32_t qh4[4] = {*(const uint32_t*)(aq), *(const uint32_t*)(aq + 8 * QKROW),
                               *(const uint32_t*)(aq + 16), *(const uint32_t*)(aq + 8 * QKROW + 16)};
            const char* al_ = Ql + (wm + gr) * QKROW + (k0 + lc2) * 2;
            uint32_t ql4[4] = {*(const uint32_t*)(al_), *(const uint32_t*)(al_ + 8 * QKROW),
                               *(const uint32_t*)(al_ + 16), *(const uint32_t*)(al_ + 8 * QKROW + 16)};
#pragma unroll
            for (int nt = 0; nt < 8; nt++) {
                const char* bk = Kh + (nt * 8 + gr) * QKROW + (k0 + lc2) * 2;
                uint32_t bh[2] = {*(const uint32_t*)(bk), *(const uint32_t*)(bk + 16)};
                const char* bk2 = Kl + (nt * 8 + gr) * QKROW + (k0 + lc2) * 2;
                uint32_t bl[2] = {*(const uint32_t*)(bk2), *(const uint32_t*)(bk2 + 16)};
                mma16816(s[nt], qh4, bh);
                mma16816(s[nt], qh4, bl);
                mma16816(s[nt], ql4, bh);
            }
        }

        // ---- causal mask on diagonal tile ----
        if (kt == qbk) {
            const int r0g = qr0 + wm + gr, r1g = r0g + 8;
#pragma unroll
            for (int nt = 0; nt < 8; nt++) {
                int col = kn0 + nt * 8 + lc2;
                if (col > r0g) s[nt][0] = -1e30f;
                if (col + 1 > r0g) s[nt][1] = -1e30f;
                if (col > r1g) s[nt][2] = -1e30f;
                if (col + 1 > r1g) s[nt][3] = -1e30f;
            }
        }

        // ---- online softmax (stats within 4-lane quad) ----
        float rm0 = -1e30f, rm1 = -1e30f;
#pragma unroll
        for (int nt = 0; nt < 8; nt++) {
            rm0 = fmaxf(rm0, fmaxf(s[nt][0], s[nt][1]));
            rm1 = fmaxf(rm1, fmaxf(s[nt][2], s[nt][3]));
        }
        rm0 = fmaxf(rm0, __shfl_xor_sync(0xFFFFFFFFu, rm0, 1));
        rm0 = fmaxf(rm0, __shfl_xor_sync(0xFFFFFFFFu, rm0, 2));
        rm1 = fmaxf(rm1, __shfl_xor_sync(0xFFFFFFFFu, rm1, 1));
        rm1 = fmaxf(rm1, __shfl_xor_sync(0xFFFFFFFFu, rm1, 2));
        float mn0 = fmaxf(m0, rm0), mn1 = fmaxf(m1, rm1);
        float al0 = __expf(m0 - mn0), al1 = __expf(m1 - mn1);
        m0 = mn0; m1 = mn1;
        l0 *= al0; l1 *= al1;
#pragma unroll
        for (int n = 0; n < 16; n++) {
            o[n][0] *= al0; o[n][1] *= al0;
            o[n][2] *= al1; o[n][3] *= al1;
        }

        // p = exp(s - m), split hi/lo, pack directly into A fragments
        uint32_t ph[4][4], pl[4][4];
#pragma unroll
        for (int t = 0; t < 8; t++) {
            float p0 = __expf(s[t][0] - mn0);
            float p1 = __expf(s[t][1] - mn0);
            float p2 = __expf(s[t][2] - mn1);
            float p3 = __expf(s[t][3] - mn1);
            l0 += p0 + p1;
            l1 += p2 + p3;
            float r0, r1, r2, r3;
            uint32_t h01 = packbf(p0, p1, r0, r1);
            uint32_t h23 = packbf(p2, p3, r2, r3);
            uint32_t lo01 = packbf2(r0, r1);
            uint32_t lo23 = packbf2(r2, r3);
            int kk = t >> 1;
            if ((t & 1) == 0) {
                ph[kk][0] = h01; ph[kk][1] = h23;
                pl[kk][0] = lo01; pl[kk][1] = lo23;
            } else {
                ph[kk][2] = h01; ph[kk][3] = h23;
                pl[kk][2] = lo01; pl[kk][3] = lo23;
            }
        }

        // ---- O += P V, 3-term split ----
#pragma unroll
        for (int nt2 = 0; nt2 < 16; nt2++) {
#pragma unroll
            for (int kk = 0; kk < 4; kk++) {
                const char* bv = Vh + (nt2 * 8 + gr) * VROW + (kk * 16 + lc2) * 2;
                uint32_t vh2[2] = {*(const uint32_t*)(bv), *(const uint32_t*)(bv + 16)};
                const char* bv2 = Vl + (nt2 * 8 + gr) * VROW + (kk * 16 + lc2) * 2;
                uint32_t vl2[2] = {*(const uint32_t*)(bv2), *(const uint32_t*)(bv2 + 16)};
                mma16816(o[nt2], ph[kk], vh2);
                mma16816(o[nt2], ph[kk], vl2);
                mma16816(o[nt2], pl[kk], vh2);
            }
        }
    }

    // ---- epilogue ----
    l0 += __shfl_xor_sync(0xFFFFFFFFu, l0, 1);
    l0 += __shfl_xor_sync(0xFFFFFFFFu, l0, 2);
    l1 += __shfl_xor_sync(0xFFFFFFFFu, l1, 1);
    l1 += __shfl_xor_sync(0xFFFFFFFFu, l1, 2);
    const float inv0 = 1.0f / l0, inv1 = 1.0f / l1;
    const int r0g = qr0 + wm + gr, r1g = r0g + 8;
#pragma unroll
    for (int nt2 = 0; nt2 < 16; nt2++) {
        int d0 = h * HD + nt2 * 8 + lc2;
        float2 v0 = {o[nt2][0] * inv0, o[nt2][1] * inv0};
        float2 v1 = {o[nt2][2] * inv1, o[nt2][3] * inv1};
        *(float2*)(ob + (size_t)r0g * EMB + d0) = v0;
        *(float2*)(ob + (size_t)r1g * EMB + d0) = v1;
    }
}

// ---------------- anchor-row top-k tile selection (fp32 path, unchanged) ----------------
__global__ void topk_kernel(const float* __restrict__ qb, const float* __restrict__ kb,
                            float* __restrict__ oidx) {
    __shared__ __align__(16) float logits[SEQ];
    __shared__ __align__(16) float qrow[HD];
    __shared__ float redm[128];
    __shared__ float tsc[32];
    const int qt = blockIdx.x, h = blockIdx.y;
    const int tid = threadIdx.x;
    const int r = qt * 128 + 127;

    qrow[tid] = qb[(size_t)r * EMB + h * HD + tid];
    __syncthreads();

    const float scale = 0.08838834764831845f;
    const float4* q4 = (const float4*)qrow;
    for (int i = 0; i < 32; i++) {
        int j = i * 128 + tid;
        float lg = NEGV;
        if (j <= r) {
            const float4* k4 = (const float4*)(kb + (size_t)j * EMB + h * HD);
            float acc = 0.f;
#pragma unroll
            for (int d = 0; d < 32; d++) {
                float4 a = q4[d];
                float4 b = k4[d];
                acc += a.x * b.x + a.y * b.y + a.z * b.z + a.w * b.w;
            }
            lg = acc * scale;
        }
        logits[j] = lg;
    }
    __syncthreads();

    float lm = -1e38f;
    for (int i = tid; i < SEQ; i += 128) lm = fmaxf(lm, logits[i]);
    redm[tid] = lm;
    __syncthreads();
    for (int st = 64; st > 0; st >>= 1) {
        if (tid < st) redm[tid] = fmaxf(redm[tid], redm[tid + st]);
        __syncthreads();
    }
    float M = redm[0];
    if (tid < 32) {
        float tm = -1e38f;
        for (int jj = 0; jj < 128; jj++) tm = fmaxf(tm, logits[tid * 128 + jj]);
        tsc[tid] = __expf(tm - M);
    }
    __syncthreads();
    if (tid == 0) {
        unsigned used = 0;
#pragma unroll
        for (int k = 0; k < 8; k++) {
            int best = 0;
            float bv = -1.f;
            for (int i = 0; i < 32; i++) {
                if (!((used >> i) & 1u) && tsc[i] > bv) { bv = tsc[i]; best = i; }
            }
            used |= 1u << best;
            oidx[(h * 32 + qt) * 8 + k] = (float)best;
        }
    }
}

// ---------------- launch ----------------
extern "C" void kernel_launch(void* const* d_in, const int* in_sizes, int n_in,
                              void* d_out, int out_size) {
    const float* x    = (const float*)d_in[0];
    const float* wq   = (const float*)d_in[1];
    const float* wk   = (const float*)d_in[2];
    const float* wv   = (const float*)d_in[3];
    const float* wo   = (const float*)d_in[4];
    const float* cosb = (const float*)d_in[5];
    const float* sinb = (const float*)d_in[6];
    float* out = (float*)d_out;

    float *qp, *kp, *vp, *ap;
    __nv_bfloat16 *xhi, *xlo, *wthi, *wtlo;
    __nv_bfloat16 *qhp, *qlp, *khp, *klp, *vthp, *vtlp;
    cudaGetSymbolAddress((void**)&qp, g_q);
    cudaGetSymbolAddress((void**)&kp, g_k);
    cudaGetSymbolAddress((void**)&vp, g_v);
    cudaGetSymbolAddress((void**)&ap, g_attn);
    cudaGetSymbolAddress((void**)&xhi, g_xhi);
    cudaGetSymbolAddress((void**)&xlo, g_xlo);
    cudaGetSymbolAddress((void**)&wthi, g_wthi);
    cudaGetSymbolAddress((void**)&wtlo, g_wtlo);
    cudaGetSymbolAddress((void**)&qhp, g_qh);
    cudaGetSymbolAddress((void**)&qlp, g_ql);
    cudaGetSymbolAddress((void**)&khp, g_kh);
    cudaGetSymbolAddress((void**)&klp, g_kl);
    cudaGetSymbolAddress((void**)&vthp, g_vth);
    cudaGetSymbolAddress((void**)&vtlp, g_vtl);

    cudaFuncSetAttribute(gemm_mma_kernel, cudaFuncAttributeMaxDynamicSharedMemorySize, GSMEM);
    cudaFuncSetAttribute(flash_hmma_kernel, cudaFuncAttributeMaxDynamicSharedMemorySize, FSMEM);

    dim3 gg(SEQ / 128, EMB / 128);  // (32, 8)
    dim3 wg(EMB / 32, EMB / 32);    // (32, 32)

    xsplit_kernel<<<SEQ * EMB / 4 / 256, 256>>>(x, xhi, xlo);

    wsplit_kernel<<<wg, 256>>>(wq, wthi, wtlo);
    gemm_mma_kernel<<<gg, 256, GSMEM>>>(xhi, xlo, wthi, wtlo, qp);
    wsplit_kernel<<<wg, 256>>>(wk, wthi, wtlo);
    gemm_mma_kernel<<<gg, 256, GSMEM>>>(xhi, xlo, wthi, wtlo, kp);
    wsplit_kernel<<<wg, 256>>>(wv, wthi, wtlo);
    gemm_mma_kernel<<<gg, 256, GSMEM>>>(xhi, xlo, wthi, wtlo, vp);

    rope_kernel<<<(2 * SEQ * NH * 64 + 255) / 256, 256>>>(cosb, sinb);

    qksplit_kernel<<<2 * SEQ * EMB / 4 / 256, 256>>>(qhp, qlp, khp, klp);
    vtsplit_kernel<<<dim3(SEQ / 32, HD / 32, NH), 256>>>(vp, vthp, vtlp);

    flash_hmma_kernel<<<dim3(SEQ / 64, NH), 128, FSMEM>>>(qhp, qlp, khp, klp, vthp, vtlp, ap);

    float* idx_out = out + (out_size - NH * 32 * 8);
    topk_kernel<<<dim3(32, NH), 128>>>(qp, kp, idx_out);

    xsplit_kernel<<<SEQ * EMB / 4 / 256, 256>>>(ap, xhi, xlo);
    wsplit_kernel<<<wg, 256>>>(wo, wthi, wtlo);
    gemm_mma_kernel<<<gg, 256, GSMEM>>>(xhi, xlo, wthi, wtlo, out);
}

// round 14
// speedup vs baseline: 3.5383x; 1.0520x over previous
#include <cuda_runtime.h>
#include <cuda_bf16.h>
#include <cstdint>

#define SEQ 4096
#define EMB 1024
#define NH  8
#define HD  128
#define NEGV -1e10f

// ---------------- scratch (no allocations allowed) ----------------
__device__ float g_q[SEQ * EMB];
__device__ float g_k[SEQ * EMB];
__device__ float g_v[SEQ * EMB];
__device__ float g_attn[SEQ * EMB];
__device__ __nv_bfloat16 g_xhi[SEQ * EMB];
__device__ __nv_bfloat16 g_xlo[SEQ * EMB];
__device__ __nv_bfloat16 g_wthi[EMB * EMB];
__device__ __nv_bfloat16 g_wtlo[EMB * EMB];
__device__ __nv_bfloat16 g_qh[SEQ * EMB];
__device__ __nv_bfloat16 g_ql[SEQ * EMB];
__device__ __nv_bfloat16 g_kh[SEQ * EMB];
__device__ __nv_bfloat16 g_kl[SEQ * EMB];
__device__ __nv_bfloat16 g_vth[EMB * SEQ];  // [h*HD+d][s]
__device__ __nv_bfloat16 g_vtl[EMB * SEQ];

// ================= helpers (target-portable PTX only) =================
__device__ __forceinline__ uint32_t smem_u32(const void* p) {
    uint32_t a;
    asm("{ .reg .u64 t; cvta.to.shared.u64 t, %1; cvt.u32.u64 %0, t; }" : "=r"(a) : "l"(p));
    return a;
}
__device__ __forceinline__ void cpa16(uint32_t dst, const void* src) {
    asm volatile("cp.async.cg.shared.global [%0], [%1], 16;" :: "r"(dst), "l"(src) : "memory");
}
#define CP_COMMIT() asm volatile("cp.async.commit_group;" ::: "memory")
#define CP_WAIT1()  asm volatile("cp.async.wait_group 1;" ::: "memory")
#define CP_WAIT0()  asm volatile("cp.async.wait_group 0;" ::: "memory")

// mma.sync m16n8k16 bf16 -> f32 accumulate (sm_80+, base-target portable)
__device__ __forceinline__ void mma16816(float* d, const uint32_t* a, const uint32_t* b) {
    asm volatile(
        "mma.sync.aligned.m16n8k16.row.col.f32.bf16.bf16.f32 "
        "{%0,%1,%2,%3}, {%4,%5,%6,%7}, {%8,%9}, {%0,%1,%2,%3};"
        : "+f"(d[0]), "+f"(d[1]), "+f"(d[2]), "+f"(d[3])
        : "r"(a[0]), "r"(a[1]), "r"(a[2]), "r"(a[3]), "r"(b[0]), "r"(b[1]));
}
// ldmatrix x4 (sm_75+, base-target portable)
__device__ __forceinline__ void ldsm4(uint32_t* r, uint32_t addr) {
    asm volatile("ldmatrix.sync.aligned.m8n8.x4.shared.b16 {%0,%1,%2,%3}, [%4];"
                 : "=r"(r[0]), "=r"(r[1]), "=r"(r[2]), "=r"(r[3]) : "r"(addr));
}

// pack two floats to bf16x2 (lo=a, hi=b), return residuals
__device__ __forceinline__ uint32_t packbf(float a, float b, float& ra, float& rb) {
    __nv_bfloat162 t;
    t.x = __float2bfloat16(a);
    t.y = __float2bfloat16(b);
    ra = a - __bfloat162float(t.x);
    rb = b - __bfloat162float(t.y);
    return *(uint32_t*)&t;
}
__device__ __forceinline__ uint32_t packbf2(float a, float b) {
    __nv_bfloat162 t;
    t.x = __float2bfloat16(a);
    t.y = __float2bfloat16(b);
    return *(uint32_t*)&t;
}

// ================= split kernels =================
__global__ void xsplit_kernel(const float* __restrict__ X, __nv_bfloat16* __restrict__ hi,
                              __nv_bfloat16* __restrict__ lo) {
    int i = blockIdx.x * 256 + threadIdx.x;  // over SEQ*EMB/4
    float4 v = ((const float4*)X)[i];
    float r0, r1, r2, r3;
    uint32_t h0 = packbf(v.x, v.y, r0, r1);
    uint32_t h1 = packbf(v.z, v.w, r2, r3);
    ((uint32_t*)hi)[2 * i] = h0;
    ((uint32_t*)hi)[2 * i + 1] = h1;
    ((uint32_t*)lo)[2 * i] = packbf2(r0, r1);
    ((uint32_t*)lo)[2 * i + 1] = packbf2(r2, r3);
}

// W[k][n] fp32 -> WT hi/lo bf16 [n][k] (transpose + split), 32x32 SMEM tiles.
__global__ void wsplit_kernel(const float* __restrict__ W, __nv_bfloat16* __restrict__ hiT,
                              __nv_bfloat16* __restrict__ loT) {
    __shared__ float t[32][33];
    const int kb = blockIdx.x * 32, nb = blockIdx.y * 32;
    const int lx = threadIdx.x & 31, ly = threadIdx.x >> 5;  // 256 thr
#pragma unroll
    for (int r = ly; r < 32; r += 8)
        t[r][lx] = W[(size_t)(kb + r) * EMB + nb + lx];
    __syncthreads();
#pragma unroll
    for (int r = ly; r < 32; r += 8) {
        float v = t[lx][r];
        __nv_bfloat16 h = __float2bfloat16(v);
        __nv_bfloat16 l = __float2bfloat16(v - __bfloat162float(h));
        hiT[(size_t)(nb + r) * EMB + kb + lx] = h;
        loT[(size_t)(nb + r) * EMB + kb + lx] = l;
    }
}

// q (scaled by 1/sqrt(D)) and k -> bf16 hi/lo splits, same [S][E] layout
__global__ void qksplit_kernel(__nv_bfloat16* __restrict__ qh, __nv_bfloat16* __restrict__ ql,
                               __nv_bfloat16* __restrict__ kh, __nv_bfloat16* __restrict__ kl) {
    int idx = blockIdx.x * 256 + threadIdx.x;  // 2 * SEQ*EMB/4 threads
    int t = idx >> 20;
    int i = idx & ((1 << 20) - 1);
    const float* src = t ? g_k : g_q;
    const float sc = t ? 1.0f : 0.08838834764831845f;
    float4 v = ((const float4*)src)[i];
    v.x *= sc; v.y *= sc; v.z *= sc; v.w *= sc;
    __nv_bfloat16* hi = t ? kh : qh;
    __nv_bfloat16* lo = t ? kl : ql;
    float r0, r1, r2, r3;
    uint32_t h0 = packbf(v.x, v.y, r0, r1);
    uint32_t h1 = packbf(v.z, v.w, r2, r3);
    ((uint32_t*)hi)[2 * i] = h0;
    ((uint32_t*)hi)[2 * i + 1] = h1;
    ((uint32_t*)lo)[2 * i] = packbf2(r0, r1);
    ((uint32_t*)lo)[2 * i + 1] = packbf2(r2, r3);
}

// V [s][h*HD+d] fp32 -> Vt hi/lo bf16 [h*HD+d][s]
__global__ void vtsplit_kernel(const float* __restrict__ V, __nv_bfloat16* __restrict__ vth,
                               __nv_bfloat16* __restrict__ vtl) {
    __shared__ float t[32][33];
    const int sb = blockIdx.x * 32, db = blockIdx.y * 32, h = blockIdx.z;
    const int lx = threadIdx.x & 31, ly = threadIdx.x >> 5;  // 256 thr
#pragma unroll
    for (int r = ly; r < 32; r += 8)
        t[r][lx] = V[(size_t)(sb + r) * EMB + h * HD + db + lx];
    __syncthreads();
#pragma unroll
    for (int r = ly; r < 32; r += 8) {
        float v = t[lx][r];
        __nv_bfloat16 hh = __float2bfloat16(v);
        __nv_bfloat16 ll = __float2bfloat16(v - __bfloat162float(hh));
        vth[(size_t)(h * HD + db + r) * SEQ + sb + lx] = hh;
        vtl[(size_t)(h * HD + db + r) * SEQ + sb + lx] = ll;
    }
}

// ================= HMMA GEMM (ldmatrix fragment loads) =================
#define KC 64
#define NCHUNK (EMB / KC)
#define ROWB 144
#define TILEB (128 * ROWB)
#define STAGEB (4 * TILEB)
#define GSMEM (2 * STAGEB)

__global__ __launch_bounds__(256, 1) void gemm_mma_kernel(
    const __nv_bfloat16* __restrict__ Ah, const __nv_bfloat16* __restrict__ Al,
    const __nv_bfloat16* __restrict__ Bh, const __nv_bfloat16* __restrict__ Bl,
    float* __restrict__ C) {
    extern __shared__ __align__(16) char sm[];
    const int tid = threadIdx.x;
    const int wid = tid >> 5, lane = tid & 31;
    const int bm = blockIdx.x * 128, bn = blockIdx.y * 128;
    const int wm = (wid & 3) * 32, wn = (wid >> 2) * 64;
    const int lr = lane >> 2, lc2 = (lane & 3) * 2;
    const uint32_t smb = smem_u32(sm);
    // ldmatrix per-lane offsets
    const int a_row = (lane & 7) + ((lane >> 3) & 1) * 8;
    const int a_kh  = ((lane >> 4) & 1) * 16;
    const int b_row = (lane & 7) + ((lane >> 4) & 1) * 8;
    const int b_kh  = ((lane >> 3) & 1) * 16;

    float acc[2][8][4];
#pragma unroll
    for (int mt = 0; mt < 2; mt++)
#pragma unroll
        for (int nt = 0; nt < 8; nt++)
#pragma unroll
            for (int e = 0; e < 4; e++) acc[mt][nt][e] = 0.f;

    auto issue = [&](int c) {
        const uint32_t sb = smb + (uint32_t)(c & 1) * STAGEB;
        const size_t koff = (size_t)c * KC;
#pragma unroll
        for (int i = 0; i < 4; i++) {
            int f = tid + i * 256;
            int r = f >> 3, seg = f & 7;
            uint32_t so = (uint32_t)(r * ROWB + seg * 16);
            const size_t ga = (size_t)(bm + r) * EMB + koff + seg * 8;
            const size_t gb = (size_t)(bn + r) * EMB + koff + seg * 8;
            cpa16(sb + 0 * TILEB + so, Ah + ga);
            cpa16(sb + 1 * TILEB + so, Al + ga);
            cpa16(sb + 2 * TILEB + so, Bh + gb);
            cpa16(sb + 3 * TILEB + so, Bl + gb);
        }
        CP_COMMIT();
    };

    issue(0);
    for (int c = 0; c < NCHUNK; c++) {
        if (c + 1 < NCHUNK) { issue(c + 1); CP_WAIT1(); }
        else                { CP_WAIT0(); }
        __syncthreads();

        const uint32_t st = smb + (uint32_t)(c & 1) * STAGEB;
        const uint32_t aAh = st + (wm + a_row) * ROWB + a_kh;
        const uint32_t aAl = st + TILEB + (wm + a_row) * ROWB + a_kh;
        const uint32_t aBh = st + 2 * TILEB + (wn + b_row) * ROWB + b_kh;
        const uint32_t aBl = st + 3 * TILEB + (wn + b_row) * ROWB + b_kh;

#pragma unroll
        for (int ks = 0; ks < 4; ks++) {
            const int kb2 = ks * 32;
            uint32_t ah[2][4], al[2][4];
            ldsm4(ah[0], aAh + kb2);
            ldsm4(ah[1], aAh + 16 * ROWB + kb2);
            ldsm4(al[0], aAl + kb2);
            ldsm4(al[1], aAl + 16 * ROWB + kb2);
#pragma unroll
            for (int nt = 0; nt < 8; nt += 2) {
                uint32_t bh4[4], bl4[4];
                ldsm4(bh4, aBh + nt * 8 * ROWB + kb2);
                ldsm4(bl4, aBl + nt * 8 * ROWB + kb2);
#pragma unroll
                for (int mt = 0; mt < 2; mt++) {
                    mma16816(acc[mt][nt], ah[mt], bh4);
                    mma16816(acc[mt][nt], ah[mt], bl4);
                    mma16816(acc[mt][nt], al[mt], bh4);
                    mma16816(acc[mt][nt + 1], ah[mt], bh4 + 2);
                    mma16816(acc[mt][nt + 1], ah[mt], bl4 + 2);
                    mma16816(acc[mt][nt + 1], al[mt], bh4 + 2);
                }
            }
        }
        __syncthreads();
    }

#pragma unroll
    for (int mt = 0; mt < 2; mt++) {
#pragma unroll
        for (int nt = 0; nt < 8; nt++) {
            int row = bm + wm + mt * 16 + lr;
            int col = bn + wn + nt * 8 + lc2;
            float2 v0 = {acc[mt][nt][0], acc[mt][nt][1]};
            float2 v1 = {acc[mt][nt][2], acc[mt][nt][3]};
            *(float2*)(C + (size_t)row * EMB + col) = v0;
            *(float2*)(C + (size_t)(row + 8) * EMB + col) = v1;
        }
    }
}

// ---------------- RoPE in-place on g_q, g_k ----------------
__global__ void rope_kernel(const float* __restrict__ cosb, const float* __restrict__ sinb) {
    int idx = blockIdx.x * blockDim.x + threadIdx.x;
    if (idx >= 2 * SEQ * NH * 64) return;
    int t = idx >> 21;
    int rem = idx & 2097151;
    int s = rem >> 9;
    int r2 = rem & 511;
    int h = r2 >> 6;
    int d = r2 & 63;
    float* p = t ? g_k : g_q;
    int base = s * EMB + h * HD + d;
    float a = p[base];
    float b = p[base + 64];
    float c = cosb[s * 64 + d];
    float sn = sinb[s * 64 + d];
    p[base] = a * c - b * sn;
    p[base + 64] = b * c + a * sn;
}

// ================= HMMA causal flash attention (ldmatrix loads) =================
#define QKROW 272
#define VROW  144
#define SQH 0
#define SQL 17408
#define SKH 34816
#define SKL 52224
#define SVH 69632
#define SVL 88064
#define FSMEM 106496

__global__ __launch_bounds__(128, 2) void flash_hmma_kernel(
    const __nv_bfloat16* __restrict__ qh_, const __nv_bfloat16* __restrict__ ql_,
    const __nv_bfloat16* __restrict__ kh_, const __nv_bfloat16* __restrict__ kl_,
    const __nv_bfloat16* __restrict__ vth_, const __nv_bfloat16* __restrict__ vtl_,
    float* __restrict__ ob) {
    extern __shared__ __align__(16) char sm[];
    const int tid = threadIdx.x;
    const int wid = tid >> 5, lane = tid & 31;
    const int gr = lane >> 2, lc2 = (lane & 3) * 2;
    const int qbk = (int)gridDim.x - 1 - (int)blockIdx.x;  // longest first
    const int h = blockIdx.y;
    const int qr0 = qbk * 64;
    const int wm = wid * 16;
    const uint32_t smb = smem_u32(sm);
    // ldmatrix per-lane offsets
    const int a_row = (lane & 7) + ((lane >> 3) & 1) * 8;
    const int a_kh  = ((lane >> 4) & 1) * 16;
    const int b_row = (lane & 7) + ((lane >> 4) & 1) * 8;
    const int b_kh  = ((lane >> 3) & 1) * 16;

    // Q tile load
#pragma unroll
    for (int i = 0; i < 8; i++) {
        int f = i * 128 + tid;
        int r = f >> 4, seg = f & 15;
        const size_t g = (size_t)(qr0 + r) * EMB + h * HD + seg * 8;
        cpa16(smb + SQH + r * QKROW + seg * 16, qh_ + g);
        cpa16(smb + SQL + r * QKROW + seg * 16, ql_ + g);
    }
    CP_COMMIT();

    float o[16][4];
#pragma unroll
    for (int n = 0; n < 16; n++)
#pragma unroll
        for (int e = 0; e < 4; e++) o[n][e] = 0.f;
    float l0 = 0.f, l1 = 0.f, m0 = -1e30f, m1 = -1e30f;

    const uint32_t qhA = smb + SQH + (wm + a_row) * QKROW + a_kh;
    const uint32_t qlA = smb + SQL + (wm + a_row) * QKROW + a_kh;
    const uint32_t khB = smb + SKH + b_row * QKROW + b_kh;
    const uint32_t klB = smb + SKL + b_row * QKROW + b_kh;
    const uint32_t vhB = smb + SVH + b_row * VROW + b_kh;
    const uint32_t vlB = smb + SVL + b_row * VROW + b_kh;

    for (int kt = 0; kt <= qbk; kt++) {
        const int kn0 = kt * 64;
        __syncthreads();  // prior PV reads of K/V done
#pragma unroll
        for (int i = 0; i < 8; i++) {
            int f = i * 128 + tid;
            int r = f >> 4, seg = f & 15;
            const size_t g = (size_t)(kn0 + r) * EMB + h * HD + seg * 8;
            cpa16(smb + SKH + r * QKROW + seg * 16, kh_ + g);
            cpa16(smb + SKL + r * QKROW + seg * 16, kl_ + g);
            int rv = f >> 3, sv = f & 7;
            const size_t gv = (size_t)(h * HD + rv) * SEQ + kn0 + sv * 8;
            cpa16(smb + SVH + rv * VROW + sv * 16, vth_ + gv);
            cpa16(smb + SVL + rv * VROW + sv * 16, vtl_ + gv);
        }
        CP_COMMIT();
        CP_WAIT0();
        __syncthreads();

        // ---- S = Q K^T (scaled), 3-term split ----
        float s[8][4];
#pragma unroll
        for (int nt = 0; nt < 8; nt++)
#pragma unroll
            for (int e = 0; e < 4; e++) s[nt][e] = 0.f;
#pragma unroll
        for (int ks = 0; ks < 8; ks++) {
            const int kb2 = ks * 32;
            uint32_t qh4[4], ql4[4];
            ldsm4(qh4, qhA + kb2);
            ldsm4(ql4, qlA + kb2);
#pragma unroll
            for (int nt = 0; nt < 8; nt += 2) {
                uint32_t bh4[4], bl4[4];
                ldsm4(bh4, khB + nt * 8 * QKROW + kb2);
                ldsm4(bl4, klB + nt * 8 * QKROW + kb2);
                mma16816(s[nt], qh4, bh4);
                mma16816(s[nt], qh4, bl4);
                mma16816(s[nt], ql4, bh4);
                mma16816(s[nt + 1], qh4, bh4 + 2);
                mma16816(s[nt + 1], qh4, bl4 + 2);
                mma16816(s[nt + 1], ql4, bh4 + 2);
            }
        }

        // ---- causal mask on diagonal tile ----
        if (kt == qbk) {
            const int r0g = qr0 + wm + gr, r1g = r0g + 8;
#pragma unroll
            for (int nt = 0; nt < 8; nt++) {
                int col = kn0 + nt * 8 + lc2;
                if (col > r0g) s[nt][0] = -1e30f;
                if (col + 1 > r0g) s[nt][1] = -1e30f;
                if (col > r1g) s[nt][2] = -1e30f;
                if (col + 1 > r1g) s[nt][3] = -1e30f;
            }
        }

        // ---- online softmax (stats within 4-lane quad) ----
        float rm0 = -1e30f, rm1 = -1e30f;
#pragma unroll
        for (int nt = 0; nt < 8; nt++) {
            rm0 = fmaxf(rm0, fmaxf(s[nt][0], s[nt][1]));
            rm1 = fmaxf(rm1, fmaxf(s[nt][2], s[nt][3]));
        }
        rm0 = fmaxf(rm0, __shfl_xor_sync(0xFFFFFFFFu, rm0, 1));
        rm0 = fmaxf(rm0, __shfl_xor_sync(0xFFFFFFFFu, rm0, 2));
        rm1 = fmaxf(rm1, __shfl_xor_sync(0xFFFFFFFFu, rm1, 1));
        rm1 = fmaxf(rm1, __shfl_xor_sync(0xFFFFFFFFu, rm1, 2));
        float mn0 = fmaxf(m0, rm0), mn1 = fmaxf(m1, rm1);
        float al0 = __expf(m0 - mn0), al1 = __expf(m1 - mn1);
        m0 = mn0; m1 = mn1;
        l0 *= al0; l1 *= al1;
#pragma unroll
        for (int n = 0; n < 16; n++) {
            o[n][0] *= al0; o[n][1] *= al0;
            o[n][2] *= al1; o[n][3] *= al1;
        }

        // p = exp(s - m), split hi/lo, pack directly into A fragments
        uint32_t ph[4][4], pl[4][4];
#pragma unroll
        for (int t = 0; t < 8; t++) {
            float p0 = __expf(s[t][0] - mn0);
            float p1 = __expf(s[t][1] - mn0);
            float p2 = __expf(s[t][2] - mn1);
            float p3 = __expf(s[t][3] - mn1);
            l0 += p0 + p1;
            l1 += p2 + p3;
            float r0, r1, r2, r3;
            uint32_t h01 = packbf(p0, p1, r0, r1);
            uint32_t h23 = packbf(p2, p3, r2, r3);
            uint32_t lo01 = packbf2(r0, r1);
            uint32_t lo23 = packbf2(r2, r3);
            int kk = t >> 1;
            if ((t & 1) == 0) {
                ph[kk][0] = h01; ph[kk][1] = h23;
                pl[kk][0] = lo01; pl[kk][1] = lo23;
            } else {
                ph[kk][2] = h01; ph[kk][3] = h23;
                pl[kk][2] = lo01; pl[kk][3] = lo23;
            }
        }

        // ---- O += P V, 3-term split ----
#pragma unroll
        for (int nt2 = 0; nt2 < 16; nt2 += 2) {
            const uint32_t vb = nt2 * 8 * VROW;
#pragma unroll
            for (int kk = 0; kk < 4; kk++) {
                uint32_t vh4[4], vl4[4];
                ldsm4(vh4, vhB + vb + kk * 32);
                ldsm4(vl4, vlB + vb + kk * 32);
                mma16816(o[nt2], ph[kk], vh4);
                mma16816(o[nt2], ph[kk], vl4);
                mma16816(o[nt2], pl[kk], vh4);
                mma16816(o[nt2 + 1], ph[kk], vh4 + 2);
                mma16816(o[nt2 + 1], ph[kk], vl4 + 2);
                mma16816(o[nt2 + 1], pl[kk], vh4 + 2);
            }
        }
    }

    // ---- epilogue ----
    l0 += __shfl_xor_sync(0xFFFFFFFFu, l0, 1);
    l0 += __shfl_xor_sync(0xFFFFFFFFu, l0, 2);
    l1 += __shfl_xor_sync(0xFFFFFFFFu, l1, 1);
    l1 += __shfl_xor_sync(0xFFFFFFFFu, l1, 2);
    const float inv0 = 1.0f / l0, inv1 = 1.0f / l1;
    const int r0g = qr0 + wm + gr, r1g = r0g + 8;
#pragma unroll
    for (int nt2 = 0; nt2 < 16; nt2++) {
        int d0 = h * HD + nt2 * 8 + lc2;
        float2 v0 = {o[nt2][0] * inv0, o[nt2][1] * inv0};
        float2 v1 = {o[nt2][2] * inv1, o[nt2][3] * inv1};
        *(float2*)(ob + (size_t)r0g * EMB + d0) = v0;
        *(float2*)(ob + (size_t)r1g * EMB + d0) = v1;
    }
}

// ---------------- anchor-row top-k tile selection (fp32 path, unchanged) ----------------
__global__ void topk_kernel(const float* __restrict__ qb, const float* __restrict__ kb,
                            float* __restrict__ oidx) {
    __shared__ __align__(16) float logits[SEQ];
    __shared__ __align__(16) float qrow[HD];
    __shared__ float redm[128];
    __shared__ float tsc[32];
    const int qt = blockIdx.x, h = blockIdx.y;
    const int tid = threadIdx.x;
    const int r = qt * 128 + 127;

    qrow[tid] = qb[(size_t)r * EMB + h * HD + tid];
    __syncthreads();

    const float scale = 0.08838834764831845f;
    const float4* q4 = (const float4*)qrow;
    for (int i = 0; i < 32; i++) {
        int j = i * 128 + tid;
        float lg = NEGV;
        if (j <= r) {
            const float4* k4 = (const float4*)(kb + (size_t)j * EMB + h * HD);
            float acc = 0.f;
#pragma unroll
            for (int d = 0; d < 32; d++) {
                float4 a = q4[d];
                float4 b = k4[d];
                acc += a.x * b.x + a.y * b.y + a.z * b.z + a.w * b.w;
            }
            lg = acc * scale;
        }
        logits[j] = lg;
    }
    __syncthreads();

    float lm = -1e38f;
    for (int i = tid; i < SEQ; i += 128) lm = fmaxf(lm, logits[i]);
    redm[tid] = lm;
    __syncthreads();
    for (int st = 64; st > 0; st >>= 1) {
        if (tid < st) redm[tid] = fmaxf(redm[tid], redm[tid + st]);
        __syncthreads();
    }
    float M = redm[0];
    if (tid < 32) {
        float tm = -1e38f;
        for (int jj = 0; jj < 128; jj++) tm = fmaxf(tm, logits[tid * 128 + jj]);
        tsc[tid] = __expf(tm - M);
    }
    __syncthreads();
    if (tid == 0) {
        unsigned used = 0;
#pragma unroll
        for (int k = 0; k < 8; k++) {
            int best = 0;
            float bv = -1.f;
            for (int i = 0; i < 32; i++) {
                if (!((used >> i) & 1u) && tsc[i] > bv) { bv = tsc[i]; best = i; }
            }
            used |= 1u << best;
            oidx[(h * 32 + qt) * 8 + k] = (float)best;
        }
    }
}

// ---------------- launch ----------------
extern "C" void kernel_launch(void* const* d_in, const int* in_sizes, int n_in,
                              void* d_out, int out_size) {
    const float* x    = (const float*)d_in[0];
    const float* wq   = (const float*)d_in[1];
    const float* wk   = (const float*)d_in[2];
    const float* wv   = (const float*)d_in[3];
    const float* wo   = (const float*)d_in[4];
    const float* cosb = (const float*)d_in[5];
    const float* sinb = (const float*)d_in[6];
    float* out = (float*)d_out;

    float *qp, *kp, *vp, *ap;
    __nv_bfloat16 *xhi, *xlo, *wthi, *wtlo;
    __nv_bfloat16 *qhp, *qlp, *khp, *klp, *vthp, *vtlp;
    cudaGetSymbolAddress((void**)&qp, g_q);
    cudaGetSymbolAddress((void**)&kp, g_k);
    cudaGetSymbolAddress((void**)&vp, g_v);
    cudaGetSymbolAddress((void**)&ap, g_attn);
    cudaGetSymbolAddress((void**)&xhi, g_xhi);
    cudaGetSymbolAddress((void**)&xlo, g_xlo);
    cudaGetSymbolAddress((void**)&wthi, g_wthi);
    cudaGetSymbolAddress((void**)&wtlo, g_wtlo);
    cudaGetSymbolAddress((void**)&qhp, g_qh);
    cudaGetSymbolAddress((void**)&qlp, g_ql);
    cudaGetSymbolAddress((void**)&khp, g_kh);
    cudaGetSymbolAddress((void**)&klp, g_kl);
    cudaGetSymbolAddress((void**)&vthp, g_vth);
    cudaGetSymbolAddress((void**)&vtlp, g_vtl);

    cudaFuncSetAttribute(gemm_mma_kernel, cudaFuncAttributeMaxDynamicSharedMemorySize, GSMEM);
    cudaFuncSetAttribute(flash_hmma_kernel, cudaFuncAttributeMaxDynamicSharedMemorySize, FSMEM);

    dim3 gg(SEQ / 128, EMB / 128);  // (32, 8)
    dim3 wg(EMB / 32, EMB / 32);    // (32, 32)

    xsplit_kernel<<<SEQ * EMB / 4 / 256, 256>>>(x, xhi, xlo);

    wsplit_kernel<<<wg, 256>>>(wq, wthi, wtlo);
    gemm_mma_kernel<<<gg, 256, GSMEM>>>(xhi, xlo, wthi, wtlo, qp);
    wsplit_kernel<<<wg, 256>>>(wk, wthi, wtlo);
    gemm_mma_kernel<<<gg, 256, GSMEM>>>(xhi, xlo, wthi, wtlo, kp);
    wsplit_kernel<<<wg, 256>>>(wv, wthi, wtlo);
    gemm_mma_kernel<<<gg, 256, GSMEM>>>(xhi, xlo, wthi, wtlo, vp);

    rope_kernel<<<(2 * SEQ * NH * 64 + 255) / 256, 256>>>(cosb, sinb);

    qksplit_kernel<<<2 * SEQ * EMB / 4 / 256, 256>>>(qhp, qlp, khp, klp);
    vtsplit_kernel<<<dim3(SEQ / 32, HD / 32, NH), 256>>>(vp, vthp, vtlp);

    flash_hmma_kernel<<<dim3(SEQ / 64, NH), 128, FSMEM>>>(qhp, qlp, khp, klp, vthp, vtlp, ap);

    float* idx_out = out + (out_size - NH * 32 * 8);
    topk_kernel<<<dim3(32, NH), 128>>>(qp, kp, idx_out);

    xsplit_kernel<<<SEQ * EMB / 4 / 256, 256>>>(ap, xhi, xlo);
    wsplit_kernel<<<wg, 256>>>(wo, wthi, wtlo);
    gemm_mma_kernel<<<gg, 256, GSMEM>>>(xhi, xlo, wthi, wtlo, out);
}